// round 2
// baseline (speedup 1.0000x reference)
#include <cuda_runtime.h>

#define NROWS 16384
#define BDIM  8192
#define DDIM  128
#define BM    128
#define BN    64
#define AS_STRIDE 132   // 128 + 4 pad: 2-way max conflict on transposed fill
#define BS_STRIDE 68    // 64 + 4 pad
#define GRID_Y 16
#define TILES_PER_BLOCK (NROWS / BN / GRID_Y)   // 16

// Scratch (allocation-free per harness rules)
__device__ float g_denom[NROWS];
__device__ float g_sppos[NROWS];

__device__ __forceinline__ const float* zrow(const float* __restrict__ za,
                                             const float* __restrict__ zb, int r) {
    return (r < BDIM) ? (za + (size_t)r * DDIM) : (zb + (size_t)(r - BDIM) * DDIM);
}

// ---- packed f32x2 helpers (sm_103a FFMA2 path) ----
__device__ __forceinline__ unsigned long long pk2(float x, float y) {
    unsigned long long p;
    asm("mov.b64 %0, {%1, %2};" : "=l"(p) : "f"(x), "f"(y));
    return p;
}
__device__ __forceinline__ void fma2(unsigned long long& d,
                                     unsigned long long a, unsigned long long b) {
    asm("fma.rn.f32x2 %0, %1, %2, %0;" : "+l"(d) : "l"(a), "l"(b));
}
__device__ __forceinline__ float2 upk2(unsigned long long p) {
    float2 r;
    asm("mov.b64 {%0, %1}, %2;" : "=f"(r.x), "=f"(r.y) : "l"(p));
    return r;
}

__global__ void init_kernel() {
    int i = blockIdx.x * blockDim.x + threadIdx.x;
    if (i < NROWS) g_denom[i] = 0.0f;
}

__device__ __forceinline__ float softplus_fast(float sim) {
    // sim > 15: log1p(e^x) == x to fp32 precision. Else MUFU-based path.
    return (sim > 15.0f) ? sim : log1pf(__expf(sim));
}

__global__ __launch_bounds__(256, 2)
void fused_kernel(const float* __restrict__ za, const float* __restrict__ zb) {
    extern __shared__ float smem[];
    float* As = smem;                        // [DDIM][AS_STRIDE], As[k*AS_STRIDE + m]
    float* Bs = smem + DDIM * AS_STRIDE;     // [DDIM][BS_STRIDE], Bs[k*BS_STRIDE + j]

    const int tid = threadIdx.x;
    const int l   = tid & 31;
    const int w   = tid >> 5;
    const int tx  = tid & 15;      // 16 col-threads
    const int ty  = tid >> 4;      // 16 row-threads
    const int R   = blockIdx.x * BM;

    // ---- Load A tile (128 rows x 128 K) transposed into smem, once per block ----
    {
        const int lr0 = w * 16 + (l & 7);
        const int lk0 = (l >> 3);
        #pragma unroll
        for (int rr = 0; rr < 2; rr++) {
            const int r = lr0 + rr * 8;
            const float* src = zrow(za, zb, R + r);
            #pragma unroll
            for (int kk = 0; kk < 8; kk++) {
                const int kq = lk0 + kk * 4;
                float4 v = *(const float4*)(src + kq * 4);
                As[(kq * 4 + 0) * AS_STRIDE + r] = v.x;
                As[(kq * 4 + 1) * AS_STRIDE + r] = v.y;
                As[(kq * 4 + 2) * AS_STRIDE + r] = v.z;
                As[(kq * 4 + 3) * AS_STRIDE + r] = v.w;
            }
        }
    }

    float rs[8];
    #pragma unroll
    for (int i = 0; i < 8; i++) rs[i] = 0.0f;

    for (int t = 0; t < TILES_PER_BLOCK; t++) {
        const int colBase = (blockIdx.y * TILES_PER_BLOCK + t) * BN;

        __syncthreads();   // protect Bs rewrite vs previous compute (also orders A fill)
        // ---- Load B tile (64 rows x 128 K) transposed ----
        {
            const int lr = w * 8 + (l & 7);
            const int lk0 = (l >> 3);
            const float* src = zrow(za, zb, colBase + lr);
            #pragma unroll
            for (int kk = 0; kk < 8; kk++) {
                const int kq = lk0 + kk * 4;
                float4 v = *(const float4*)(src + kq * 4);
                Bs[(kq * 4 + 0) * BS_STRIDE + lr] = v.x;
                Bs[(kq * 4 + 1) * BS_STRIDE + lr] = v.y;
                Bs[(kq * 4 + 2) * BS_STRIDE + lr] = v.z;
                Bs[(kq * 4 + 3) * BS_STRIDE + lr] = v.w;
            }
        }
        __syncthreads();

        // ---- 8x4 micro-tile GEMM with f32x2 packed FMA (rows packed in pairs) ----
        unsigned long long acc[4][4];
        #pragma unroll
        for (int i = 0; i < 4; i++)
            #pragma unroll
            for (int c = 0; c < 4; c++) acc[i][c] = 0ull;

        #pragma unroll 8
        for (int k = 0; k < DDIM; k++) {
            // rows ty*8 .. ty*8+7 at this k, as 4 packed row-pairs (free packing)
            ulonglong2 a01 = *(const ulonglong2*)(As + k * AS_STRIDE + ty * 8);
            ulonglong2 a23 = *(const ulonglong2*)(As + k * AS_STRIDE + ty * 8 + 4);
            float4 b = *(const float4*)(Bs + k * BS_STRIDE + tx * 4);
            unsigned long long bd0 = pk2(b.x, b.x);
            unsigned long long bd1 = pk2(b.y, b.y);
            unsigned long long bd2 = pk2(b.z, b.z);
            unsigned long long bd3 = pk2(b.w, b.w);
            unsigned long long ap[4] = { a01.x, a01.y, a23.x, a23.y };
            #pragma unroll
            for (int i = 0; i < 4; i++) {
                fma2(acc[i][0], ap[i], bd0);
                fma2(acc[i][1], ap[i], bd1);
                fma2(acc[i][2], ap[i], bd2);
                fma2(acc[i][3], ap[i], bd3);
            }
        }

        // ---- Fused epilogue: softplus, diag-zero, positive capture, row sums ----
        #pragma unroll
        for (int i = 0; i < 4; i++) {
            const int row0 = R + ty * 8 + i * 2;
            #pragma unroll
            for (int c = 0; c < 4; c++) {
                float2 v = upk2(acc[i][c]);
                const int col = colBase + tx * 4 + c;
                {
                    float sp = softplus_fast(v.x * 2.0f);    // /TAU, TAU=0.5
                    if (row0 == col) sp = 0.0f;
                    if (col == (row0 ^ BDIM)) g_sppos[row0] = sp;
                    rs[i * 2] += sp;
                }
                {
                    const int row1 = row0 + 1;
                    float sp = softplus_fast(v.y * 2.0f);
                    if (row1 == col) sp = 0.0f;
                    if (col == (row1 ^ BDIM)) g_sppos[row1] = sp;
                    rs[i * 2 + 1] += sp;
                }
            }
        }
    }

    // ---- Reduce row sums across the 16 col-threads sharing each row ----
    #pragma unroll
    for (int i = 0; i < 8; i++) {
        float v = rs[i];
        v += __shfl_down_sync(0xffffffffu, v, 8, 16);
        v += __shfl_down_sync(0xffffffffu, v, 4, 16);
        v += __shfl_down_sync(0xffffffffu, v, 2, 16);
        v += __shfl_down_sync(0xffffffffu, v, 1, 16);
        if (tx == 0) atomicAdd(&g_denom[R + ty * 8 + i], v);
    }
}

__global__ void finalize_kernel(float* __restrict__ out) {
    __shared__ double red[256];
    double s = 0.0;
    for (int i = threadIdx.x; i < NROWS; i += 256) {
        float spp = fmaxf(g_sppos[i], 1e-8f);
        float den = fmaxf(g_denom[i], 1e-8f);
        s += (double)(logf(spp) - logf(den));
    }
    red[threadIdx.x] = s;
    __syncthreads();
    for (int o = 128; o > 0; o >>= 1) {
        if (threadIdx.x < o) red[threadIdx.x] += red[threadIdx.x + o];
        __syncthreads();
    }
    if (threadIdx.x == 0) out[0] = (float)(-red[0] / (double)NROWS);
}

extern "C" void kernel_launch(void* const* d_in, const int* in_sizes, int n_in,
                              void* d_out, int out_size) {
    const float* za = (const float*)d_in[0];
    const float* zb = (const float*)d_in[1];
    float* out = (float*)d_out;

    const size_t smem_bytes = (size_t)(DDIM * AS_STRIDE + DDIM * BS_STRIDE) * sizeof(float); // 100 KB
    cudaFuncSetAttribute(fused_kernel, cudaFuncAttributeMaxDynamicSharedMemorySize,
                         (int)smem_bytes);

    init_kernel<<<NROWS / 256, 256>>>();
    dim3 grid(NROWS / BM, GRID_Y);    // 128 x 16 = 2048 blocks
    fused_kernel<<<grid, 256, smem_bytes>>>(za, zb);
    finalize_kernel<<<1, 256>>>(out);
}

// round 5
// speedup vs baseline: 5.3133x; 5.3133x over previous
#include <cuda_runtime.h>
#include <cuda_bf16.h>
#include <cstdint>

#define NROWS 16384
#define BDIM  8192
#define DDIM  128
#define BM    128
#define BN    128
#define GRID_Y 16
#define TILES_PER_BLOCK 8        // 16384 / BN / GRID_Y
#define THREADS 512

#define SM_A   0
#define SM_B0  32768
#define SM_B1  65536
#define SM_TOTAL 98304           // 96 KB dynamic smem

// allocation-free scratch
__device__ float g_denom[NROWS];
__device__ float g_sppos[NROWS];
__device__ __nv_bfloat16 g_z[NROWS * DDIM];   // 4 MB, L2-resident

// ---------------- helpers ----------------
__device__ __forceinline__ uint32_t smem_u32(const void* p) {
    uint32_t a;
    asm("{ .reg .u64 t; cvta.to.shared.u64 t, %1; cvt.u32.u64 %0, t; }" : "=r"(a) : "l"(p));
    return a;
}

#define LDSM4(r, addr) \
    asm volatile("ldmatrix.sync.aligned.m8n8.x4.shared.b16 {%0,%1,%2,%3}, [%4];" \
        : "=r"((r)[0]), "=r"((r)[1]), "=r"((r)[2]), "=r"((r)[3]) : "r"(addr))

#define MMA16816(d, a, b0, b1) \
    asm volatile("mma.sync.aligned.m16n8k16.row.col.f32.bf16.bf16.f32 " \
        "{%0,%1,%2,%3}, {%4,%5,%6,%7}, {%8,%9}, {%0,%1,%2,%3};" \
        : "+f"((d)[0]), "+f"((d)[1]), "+f"((d)[2]), "+f"((d)[3]) \
        : "r"((a)[0]), "r"((a)[1]), "r"((a)[2]), "r"((a)[3]), "r"(b0), "r"(b1))

// Issue one 128x128 bf16 tile load: 2048 x 16B cp.async, XOR-swizzled rows.
// smem row = 256 B (128 bf16); 16B chunk c stored at c ^ (row & 7).
__device__ __forceinline__ void load_tile_async(uint32_t sdst, const __nv_bfloat16* gsrc, int tid) {
    #pragma unroll
    for (int it = 0; it < 4; it++) {
        int i = tid + it * THREADS;          // 0..2047
        int row = i >> 4, c = i & 15;
        uint32_t dst = sdst + (uint32_t)(row * 256 + ((c ^ (row & 7)) * 16));
        const void* src = gsrc + (size_t)row * DDIM + c * 8;
        asm volatile("cp.async.cg.shared.global [%0], [%1], 16;" :: "r"(dst), "l"(src));
    }
}

// ---------------- kernels ----------------
__global__ void convert_kernel(const float* __restrict__ za, const float* __restrict__ zb) {
    int i4 = blockIdx.x * blockDim.x + threadIdx.x;      // one float4 per thread
    if (i4 >= NROWS * DDIM / 4) return;
    float4 v = (i4 < BDIM * DDIM / 4) ? ((const float4*)za)[i4]
                                      : ((const float4*)zb)[i4 - BDIM * DDIM / 4];
    __nv_bfloat162 lo = __nv_bfloat162(__float2bfloat16(v.x), __float2bfloat16(v.y));
    __nv_bfloat162 hi = __nv_bfloat162(__float2bfloat16(v.z), __float2bfloat16(v.w));
    ((__nv_bfloat162*)g_z)[i4 * 2]     = lo;
    ((__nv_bfloat162*)g_z)[i4 * 2 + 1] = hi;
}

__global__ void init_kernel() {
    int i = blockIdx.x * blockDim.x + threadIdx.x;
    if (i < NROWS) g_denom[i] = 0.0f;
}

__global__ __launch_bounds__(THREADS, 1)
void fused_mma_kernel() {
    extern __shared__ char smem[];
    const uint32_t sbase = smem_u32(smem);
    const int tid    = threadIdx.x;
    const int lane   = tid & 31;
    const int wid    = tid >> 5;
    const int warp_m = wid >> 2;           // 0..3 : 32-row block
    const int warp_n = wid & 3;            // 0..3 : 32-col block
    const int R        = blockIdx.x * BM;
    const int colBase0 = blockIdx.y * (TILES_PER_BLOCK * BN);

    // ldmatrix per-thread address components (non-trans, K-major both operands)
    const int a_row = warp_m * 32 + (lane & 7) + ((lane >> 3) & 1) * 8;  // + mt*16
    const int a_kc  = lane >> 4;                                          // 8-col chunk within k-step
    const int b_row = warp_n * 32 + (lane & 7) + ((lane >> 4) & 1) * 8;  // + p*16
    const int b_kc  = (lane >> 3) & 1;

    // prologue: A tile + B tile 0 in one cp.async group
    load_tile_async(sbase + SM_A,  g_z + (size_t)R * DDIM, tid);
    load_tile_async(sbase + SM_B0, g_z + (size_t)colBase0 * DDIM, tid);
    asm volatile("cp.async.commit_group;" ::: "memory");
    asm volatile("cp.async.wait_group 0;" ::: "memory");
    __syncthreads();

    float rsum[2][2] = {{0.0f, 0.0f}, {0.0f, 0.0f}};

    for (int t = 0; t < TILES_PER_BLOCK; t++) {
        // prefetch next B tile into the other buffer
        if (t + 1 < TILES_PER_BLOCK) {
            load_tile_async(sbase + SM_B0 + (uint32_t)((t + 1) & 1) * 32768u,
                            g_z + (size_t)(colBase0 + (t + 1) * BN) * DDIM, tid);
            asm volatile("cp.async.commit_group;" ::: "memory");
        }

        const uint32_t bbase = sbase + SM_B0 + (uint32_t)(t & 1) * 32768u;
        float acc[2][4][4];
        #pragma unroll
        for (int mt = 0; mt < 2; mt++)
            #pragma unroll
            for (int nt = 0; nt < 4; nt++)
                #pragma unroll
                for (int i = 0; i < 4; i++) acc[mt][nt][i] = 0.0f;

        #pragma unroll
        for (int ks = 0; ks < 8; ks++) {
            uint32_t a[2][4], b[2][4];
            #pragma unroll
            for (int mt = 0; mt < 2; mt++) {
                int row = a_row + mt * 16;
                int ch  = (ks * 2 + a_kc) ^ (row & 7);
                LDSM4(a[mt], sbase + SM_A + (uint32_t)(row * 256 + ch * 16));
            }
            #pragma unroll
            for (int p = 0; p < 2; p++) {
                int row = b_row + p * 16;
                int ch  = (ks * 2 + b_kc) ^ (row & 7);
                LDSM4(b[p], bbase + (uint32_t)(row * 256 + ch * 16));
            }
            #pragma unroll
            for (int mt = 0; mt < 2; mt++)
                #pragma unroll
                for (int nt = 0; nt < 4; nt++)
                    MMA16816(acc[mt][nt], a[mt], b[nt >> 1][(nt & 1) * 2], b[nt >> 1][(nt & 1) * 2 + 1]);
        }

        // fused epilogue on register accumulators
        const int cb = colBase0 + t * BN + warp_n * 32;
        #pragma unroll
        for (int mt = 0; mt < 2; mt++) {
            const int rb = R + warp_m * 32 + mt * 16 + (lane >> 2);
            #pragma unroll
            for (int nt = 0; nt < 4; nt++) {
                #pragma unroll
                for (int i = 0; i < 4; i++) {
                    const int row = rb + ((i >> 1) ? 8 : 0);
                    const int col = cb + nt * 8 + (lane & 3) * 2 + (i & 1);
                    float x = acc[mt][nt][i] * 2.0f;           // sim / tau, tau = 0.5
                    float e;
                    asm("ex2.approx.ftz.f32 %0, %1;" : "=f"(e) : "f"(x * 1.4426950408889634f));
                    float l;
                    asm("lg2.approx.ftz.f32 %0, %1;" : "=f"(l) : "f"(1.0f + e));
                    float sp  = 0.6931471805599453f * l;       // ln2 * lg2(1+e^x)
                    float spn = __fmaf_rn(-0.5f * e, e, e);    // e^x - e^2x/2 for very negative x
                    sp = (x < -9.0f) ? spn : sp;
                    sp = (x > 15.0f) ? x : sp;
                    if (col == row) sp = 0.0f;                 // zero diagonal
                    if (col == (row ^ BDIM)) g_sppos[row] = sp;  // positive-pair capture
                    rsum[mt][i >> 1] += sp;
                }
            }
        }

        if (t + 1 < TILES_PER_BLOCK) {
            asm volatile("cp.async.wait_group 0;" ::: "memory");
            __syncthreads();
        }
    }

    // row-sum reduce: quad shuffle -> smem across warp_n -> one atomic per row
    __syncthreads();                        // B buffers dead; reuse as scratch
    float* sums = (float*)(smem + SM_B0);   // [4][128]
    #pragma unroll
    for (int mt = 0; mt < 2; mt++)
        #pragma unroll
        for (int h = 0; h < 2; h++) {
            float v = rsum[mt][h];
            v += __shfl_xor_sync(0xffffffffu, v, 1);
            v += __shfl_xor_sync(0xffffffffu, v, 2);
            if ((lane & 3) == 0)
                sums[warp_n * 128 + warp_m * 32 + mt * 16 + (lane >> 2) + h * 8] = v;
        }
    __syncthreads();
    if (tid < 128) {
        float tot = sums[tid] + sums[128 + tid] + sums[256 + tid] + sums[384 + tid];
        atomicAdd(&g_denom[R + tid], tot);
    }
}

__global__ void finalize_kernel(float* __restrict__ out) {
    __shared__ double red[256];
    double s = 0.0;
    for (int i = threadIdx.x; i < NROWS; i += 256) {
        float spp = fmaxf(g_sppos[i], 1e-8f);
        float den = fmaxf(g_denom[i], 1e-8f);
        s += (double)(logf(spp) - logf(den));
    }
    red[threadIdx.x] = s;
    __syncthreads();
    for (int o = 128; o > 0; o >>= 1) {
        if (threadIdx.x < o) red[threadIdx.x] += red[threadIdx.x + o];
        __syncthreads();
    }
    if (threadIdx.x == 0) out[0] = (float)(-red[0] / (double)NROWS);
}

extern "C" void kernel_launch(void* const* d_in, const int* in_sizes, int n_in,
                              void* d_out, int out_size) {
    const float* za = (const float*)d_in[0];
    const float* zb = (const float*)d_in[1];
    float* out = (float*)d_out;

    cudaFuncSetAttribute(fused_mma_kernel, cudaFuncAttributeMaxDynamicSharedMemorySize, SM_TOTAL);

    convert_kernel<<<(NROWS * DDIM / 4 + 255) / 256, 256>>>(za, zb);
    init_kernel<<<NROWS / 256, 256>>>();
    dim3 grid(NROWS / BM, GRID_Y);     // 128 x 16 = 2048 CTAs
    fused_mma_kernel<<<grid, THREADS, SM_TOTAL>>>();
    finalize_kernel<<<1, 256>>>(out);
}

// round 6
// speedup vs baseline: 10.3328x; 1.9447x over previous
#include <cuda_runtime.h>
#include <cuda_bf16.h>
#include <cstdint>

#define NROWS 16384
#define BDIM  8192
#define DDIM  128
#define THREADS 512
#define SM_A   0
#define SM_B   32768
#define SM_TOTAL 65536        // 64 KB -> 2 CTAs/SM

// allocation-free scratch
__device__ float  g_denom[NROWS];
__device__ float  g_sppos[NROWS];
__device__ double g_total;
__device__ __nv_bfloat16 g_z[NROWS * DDIM];   // 4 MB, L2-resident

// ---------------- helpers ----------------
__device__ __forceinline__ uint32_t smem_u32(const void* p) {
    uint32_t a;
    asm("{ .reg .u64 t; cvta.to.shared.u64 t, %1; cvt.u32.u64 %0, t; }" : "=r"(a) : "l"(p));
    return a;
}
#define LDSM4(r, addr) \
    asm volatile("ldmatrix.sync.aligned.m8n8.x4.shared.b16 {%0,%1,%2,%3}, [%4];" \
        : "=r"((r)[0]), "=r"((r)[1]), "=r"((r)[2]), "=r"((r)[3]) : "r"(addr))
#define MMA16816(d, a, b0, b1) \
    asm volatile("mma.sync.aligned.m16n8k16.row.col.f32.bf16.bf16.f32 " \
        "{%0,%1,%2,%3}, {%4,%5,%6,%7}, {%8,%9}, {%0,%1,%2,%3};" \
        : "+f"((d)[0]), "+f"((d)[1]), "+f"((d)[2]), "+f"((d)[3]) \
        : "r"((a)[0]), "r"((a)[1]), "r"((a)[2]), "r"((a)[3]), "r"(b0), "r"(b1))

// 128x128 bf16 tile: smem row = 256B, 16B chunk c stored at c ^ (row & 7)
__device__ __forceinline__ void load_tile_async(uint32_t sdst, const __nv_bfloat16* gsrc, int tid) {
    #pragma unroll
    for (int it = 0; it < 4; it++) {
        int i = tid + it * THREADS;          // 0..2047
        int row = i >> 4, c = i & 15;
        uint32_t dst = sdst + (uint32_t)(row * 256 + ((c ^ (row & 7)) * 16));
        const void* src = gsrc + (size_t)row * DDIM + c * 8;
        asm volatile("cp.async.cg.shared.global [%0], [%1], 16;" :: "r"(dst), "l"(src));
    }
}

// ---------------- small kernels ----------------
__global__ void convert_kernel(const float* __restrict__ za, const float* __restrict__ zb) {
    int i4 = blockIdx.x * blockDim.x + threadIdx.x;
    if (i4 >= NROWS * DDIM / 4) return;
    float4 v = (i4 < BDIM * DDIM / 4) ? ((const float4*)za)[i4]
                                      : ((const float4*)zb)[i4 - BDIM * DDIM / 4];
    ((__nv_bfloat162*)g_z)[i4 * 2]     = __nv_bfloat162(__float2bfloat16(v.x), __float2bfloat16(v.y));
    ((__nv_bfloat162*)g_z)[i4 * 2 + 1] = __nv_bfloat162(__float2bfloat16(v.z), __float2bfloat16(v.w));
}

__global__ void init_kernel() {
    int i = blockIdx.x * blockDim.x + threadIdx.x;
    if (i < NROWS) g_denom[i] = 0.0f;
    if (i == 0) g_total = 0.0;
}

// ---------------- fused triangular kernel ----------------
template<bool DIAG, bool POS>
__device__ __forceinline__ void tile_work(int bi, int bj, char* smem, uint32_t sbase, int tid) {
    const int lane   = tid & 31;
    const int wid    = tid >> 5;
    const int warp_m = wid >> 2;
    const int warp_n = wid & 3;

    load_tile_async(sbase + SM_A, g_z + (size_t)bi * 128 * DDIM, tid);
    load_tile_async(sbase + SM_B, g_z + (size_t)bj * 128 * DDIM, tid);
    asm volatile("cp.async.commit_group;" ::: "memory");
    asm volatile("cp.async.wait_group 0;" ::: "memory");
    __syncthreads();

    const int a_row = warp_m * 32 + (lane & 7) + ((lane >> 3) & 1) * 8;   // + mt*16
    const int a_kc  = lane >> 4;
    const int b_rw  = warp_n * 32 + (lane & 7) + ((lane >> 4) & 1) * 8;   // + nth*16
    const int b_kc  = (lane >> 3) & 1;

    float rsum[2][2] = {{0.f, 0.f}, {0.f, 0.f}};
    float csum[8]    = {0.f, 0.f, 0.f, 0.f, 0.f, 0.f, 0.f, 0.f};

    #pragma unroll
    for (int nth = 0; nth < 2; nth++) {       // N half-pass: 16 cols each, keeps regs low
        float acc[2][2][4];
        #pragma unroll
        for (int mt = 0; mt < 2; mt++)
            #pragma unroll
            for (int nl = 0; nl < 2; nl++)
                #pragma unroll
                for (int i = 0; i < 4; i++) acc[mt][nl][i] = 0.f;

        #pragma unroll
        for (int ks = 0; ks < 8; ks++) {
            uint32_t a[2][4], b[4];
            #pragma unroll
            for (int mt = 0; mt < 2; mt++) {
                int row = a_row + mt * 16;
                int ch  = (ks * 2 + a_kc) ^ (row & 7);
                LDSM4(a[mt], sbase + SM_A + (uint32_t)(row * 256 + ch * 16));
            }
            {
                int row = b_rw + nth * 16;
                int ch  = (ks * 2 + b_kc) ^ (row & 7);
                LDSM4(b, sbase + SM_B + (uint32_t)(row * 256 + ch * 16));
            }
            #pragma unroll
            for (int mt = 0; mt < 2; mt++)
                #pragma unroll
                for (int nl = 0; nl < 2; nl++)
                    MMA16816(acc[mt][nl], a[mt], b[nl * 2], b[nl * 2 + 1]);
        }

        // fused epilogue on this half
        #pragma unroll
        for (int mt = 0; mt < 2; mt++)
            #pragma unroll
            for (int nl = 0; nl < 2; nl++)
                #pragma unroll
                for (int i = 0; i < 4; i++) {
                    float v = acc[mt][nl][i];
                    float x = v + v;                          // sim / tau, tau = 0.5
                    float y = x * 1.4426950408889634f;
                    float e;
                    asm("ex2.approx.ftz.f32 %0, %1;" : "=f"(e) : "f"(y));
                    float l;
                    asm("lg2.approx.ftz.f32 %0, %1;" : "=f"(l) : "f"(1.0f + e));
                    float sp  = 0.6931471805599453f * l;
                    float spn = __fmaf_rn(-0.5f * e, e, e);   // x << 0: e^x - e^2x/2
                    sp = (x < -9.0f) ? spn : sp;
                    sp = (x > 15.0f) ? x : sp;
                    if (DIAG || POS) {
                        const int lr = warp_m * 32 + mt * 16 + (lane >> 2) + (i >> 1) * 8;
                        const int lc = warp_n * 32 + (nth * 2 + nl) * 8 + (lane & 3) * 2 + (i & 1);
                        if (DIAG) { if (lr == lc) sp = 0.0f; }
                        if (POS)  { if (lr == lc) {            // col == row ^ 8192 here
                            g_sppos[bi * 128 + lr] = sp;
                            g_sppos[bj * 128 + lc] = sp;
                        } }
                    }
                    rsum[mt][i >> 1] += sp;
                    if (!DIAG) csum[(nth * 2 + nl) * 2 + (i & 1)] += sp;
                }
    }

    // ---- reductions (A/B smem dead now) ----
    __syncthreads();
    float* srow = (float*)(smem);          // [4(warp_n)][128]
    float* scol = (float*)(smem + 2048);   // [4(warp_m)][128]
    #pragma unroll
    for (int mt = 0; mt < 2; mt++)
        #pragma unroll
        for (int h = 0; h < 2; h++) {
            float v = rsum[mt][h];
            v += __shfl_xor_sync(0xffffffffu, v, 1);
            v += __shfl_xor_sync(0xffffffffu, v, 2);
            if ((lane & 3) == 0)
                srow[warp_n * 128 + warp_m * 32 + mt * 16 + (lane >> 2) + h * 8] = v;
        }
    if (!DIAG) {
        #pragma unroll
        for (int c8 = 0; c8 < 8; c8++) {
            float v = csum[c8];
            v += __shfl_xor_sync(0xffffffffu, v, 4);
            v += __shfl_xor_sync(0xffffffffu, v, 8);
            v += __shfl_xor_sync(0xffffffffu, v, 16);
            if (lane < 4)
                scol[warp_m * 128 + warp_n * 32 + (c8 >> 1) * 8 + lane * 2 + (c8 & 1)] = v;
        }
    }
    __syncthreads();
    if (tid < 128) {
        float rt = srow[tid] + srow[128 + tid] + srow[256 + tid] + srow[384 + tid];
        atomicAdd(&g_denom[bi * 128 + tid], rt);
        if (!DIAG) {
            float ct = scol[tid] + scol[128 + tid] + scol[256 + tid] + scol[384 + tid];
            atomicAdd(&g_denom[bj * 128 + tid], ct);
        }
    }
}

__global__ __launch_bounds__(THREADS, 2)
void fused_tri_kernel() {
    const int bj = blockIdx.x, bi = blockIdx.y;
    if (bj < bi) return;                       // upper triangle only
    extern __shared__ char smem[];
    const uint32_t sbase = smem_u32(smem);
    if (bi == bj)            tile_work<true,  false>(bi, bj, smem, sbase, threadIdx.x);
    else if (bj == bi + 64)  tile_work<false, true >(bi, bj, smem, sbase, threadIdx.x);
    else                     tile_work<false, false>(bi, bj, smem, sbase, threadIdx.x);
}

// ---------------- parallel finalize ----------------
__global__ void finalize_part() {
    __shared__ double red[256];
    const int i = blockIdx.x * 256 + threadIdx.x;     // 64*256 == NROWS exactly
    float spp = fmaxf(g_sppos[i], 1e-8f);
    float den = fmaxf(g_denom[i], 1e-8f);
    red[threadIdx.x] = (double)(logf(spp) - logf(den));
    __syncthreads();
    for (int o = 128; o > 0; o >>= 1) {
        if (threadIdx.x < o) red[threadIdx.x] += red[threadIdx.x + o];
        __syncthreads();
    }
    if (threadIdx.x == 0) atomicAdd(&g_total, red[0]);
}

__global__ void finalize_write(float* __restrict__ out) {
    out[0] = (float)(-g_total / (double)NROWS);
}

extern "C" void kernel_launch(void* const* d_in, const int* in_sizes, int n_in,
                              void* d_out, int out_size) {
    const float* za = (const float*)d_in[0];
    const float* zb = (const float*)d_in[1];
    float* out = (float*)d_out;

    cudaFuncSetAttribute(fused_tri_kernel, cudaFuncAttributeMaxDynamicSharedMemorySize, SM_TOTAL);

    convert_kernel<<<(NROWS * DDIM / 4 + 255) / 256, 256>>>(za, zb);
    init_kernel<<<NROWS / 256, 256>>>();
    dim3 grid(128, 128);                  // upper-triangle CTAs do work; rest exit
    fused_tri_kernel<<<grid, THREADS, SM_TOTAL>>>();
    finalize_part<<<64, 256>>>();
    finalize_write<<<1, 1>>>(out);
}

// round 7
// speedup vs baseline: 11.7909x; 1.1411x over previous
#include <cuda_runtime.h>
#include <cuda_bf16.h>
#include <cstdint>

#define NROWS 16384
#define BDIM  8192
#define DDIM  128
#define THREADS 256
#define SM_A   0
#define SM_B   32768
#define SM_TOTAL 65536        // 64 KB -> 2 CTAs/SM

// allocation-free scratch
__device__ float  g_denom[NROWS];
__device__ float  g_sppos[NROWS];
__device__ double g_total;
__device__ __nv_bfloat16 g_z[NROWS * DDIM];   // 4 MB, L2-resident

// ---------------- helpers ----------------
__device__ __forceinline__ uint32_t smem_u32(const void* p) {
    uint32_t a;
    asm("{ .reg .u64 t; cvta.to.shared.u64 t, %1; cvt.u32.u64 %0, t; }" : "=r"(a) : "l"(p));
    return a;
}
#define LDSM4(r, addr) \
    asm volatile("ldmatrix.sync.aligned.m8n8.x4.shared.b16 {%0,%1,%2,%3}, [%4];" \
        : "=r"((r)[0]), "=r"((r)[1]), "=r"((r)[2]), "=r"((r)[3]) : "r"(addr))
#define MMA16816(d, a, b0, b1) \
    asm volatile("mma.sync.aligned.m16n8k16.row.col.f32.bf16.bf16.f32 " \
        "{%0,%1,%2,%3}, {%4,%5,%6,%7}, {%8,%9}, {%0,%1,%2,%3};" \
        : "+f"((d)[0]), "+f"((d)[1]), "+f"((d)[2]), "+f"((d)[3]) \
        : "r"((a)[0]), "r"((a)[1]), "r"((a)[2]), "r"((a)[3]), "r"(b0), "r"(b1))

// 128x128 bf16 tile: smem row = 256B, 16B chunk c stored at c ^ (row & 7)
__device__ __forceinline__ void load_tile_async(uint32_t sdst, const __nv_bfloat16* gsrc, int tid) {
    #pragma unroll
    for (int it = 0; it < 8; it++) {
        int i = tid + it * THREADS;          // 0..2047
        int row = i >> 4, c = i & 15;
        uint32_t dst = sdst + (uint32_t)(row * 256 + ((c ^ (row & 7)) * 16));
        const void* src = gsrc + (size_t)row * DDIM + c * 8;
        asm volatile("cp.async.cg.shared.global [%0], [%1], 16;" :: "r"(dst), "l"(src));
    }
}

// ---------------- convert + init (merged) ----------------
__global__ void convert_kernel(const float* __restrict__ za, const float* __restrict__ zb) {
    int i4 = blockIdx.x * blockDim.x + threadIdx.x;
    if (i4 < NROWS) g_denom[i4] = 0.0f;
    if (i4 == 0) g_total = 0.0;
    if (i4 >= NROWS * DDIM / 4) return;
    float4 v = (i4 < BDIM * DDIM / 4) ? ((const float4*)za)[i4]
                                      : ((const float4*)zb)[i4 - BDIM * DDIM / 4];
    ((__nv_bfloat162*)g_z)[i4 * 2]     = __nv_bfloat162(__float2bfloat16(v.x), __float2bfloat16(v.y));
    ((__nv_bfloat162*)g_z)[i4 * 2 + 1] = __nv_bfloat162(__float2bfloat16(v.z), __float2bfloat16(v.w));
}

// ---------------- fused triangular kernel ----------------
template<bool DIAG, bool POS>
__device__ __forceinline__ void tile_work(int bi, int bj, char* smem, uint32_t sbase, int tid) {
    const int lane   = tid & 31;
    const int wid    = tid >> 5;
    const int warp_m = wid & 3;            // 4 row blocks of 32
    const int warp_n = wid >> 2;           // 2 col blocks of 64

    load_tile_async(sbase + SM_A, g_z + (size_t)bi * 128 * DDIM, tid);
    load_tile_async(sbase + SM_B, g_z + (size_t)bj * 128 * DDIM, tid);
    asm volatile("cp.async.commit_group;" ::: "memory");
    asm volatile("cp.async.wait_group 0;" ::: "memory");
    __syncthreads();

    const int a_row = warp_m * 32 + (lane & 7) + ((lane >> 3) & 1) * 8;   // + mt*16
    const int a_kc  = lane >> 4;
    const int b_row = warp_n * 64 + (lane & 7) + ((lane >> 4) & 1) * 8;   // + g*16
    const int b_kc  = (lane >> 3) & 1;

    float acc[2][8][4];
    #pragma unroll
    for (int mt = 0; mt < 2; mt++)
        #pragma unroll
        for (int nl = 0; nl < 8; nl++)
            #pragma unroll
            for (int i = 0; i < 4; i++) acc[mt][nl][i] = 0.f;

    #pragma unroll
    for (int ks = 0; ks < 8; ks++) {
        uint32_t a[2][4], b[4][4];
        #pragma unroll
        for (int mt = 0; mt < 2; mt++) {
            int row = a_row + mt * 16;
            int ch  = (ks * 2 + a_kc) ^ (row & 7);
            LDSM4(a[mt], sbase + SM_A + (uint32_t)(row * 256 + ch * 16));
        }
        #pragma unroll
        for (int g = 0; g < 4; g++) {
            int row = b_row + g * 16;
            int ch  = (ks * 2 + b_kc) ^ (row & 7);
            LDSM4(b[g], sbase + SM_B + (uint32_t)(row * 256 + ch * 16));
        }
        #pragma unroll
        for (int mt = 0; mt < 2; mt++)
            #pragma unroll
            for (int nl = 0; nl < 8; nl++)
                MMA16816(acc[mt][nl], a[mt], b[nl >> 1][(nl & 1) * 2], b[nl >> 1][(nl & 1) * 2 + 1]);
    }

    // ---- fused epilogue ----
    float rsum[2][2] = {{0.f, 0.f}, {0.f, 0.f}};
    float csum[16];
    #pragma unroll
    for (int c = 0; c < 16; c++) csum[c] = 0.f;

    #pragma unroll
    for (int mt = 0; mt < 2; mt++)
        #pragma unroll
        for (int nl = 0; nl < 8; nl++)
            #pragma unroll
            for (int i = 0; i < 4; i++) {
                float v = acc[mt][nl][i];
                float x = v + v;                          // sim / tau, tau = 0.5
                float e;
                asm("ex2.approx.ftz.f32 %0, %1;" : "=f"(e) : "f"(x * 1.4426950408889634f));
                float l;
                asm("lg2.approx.ftz.f32 %0, %1;" : "=f"(l) : "f"(1.0f + e));
                float sp  = 0.6931471805599453f * l;
                float spn = __fmaf_rn(-0.5f * e, e, e);   // x << 0: e^x - e^2x/2
                sp = (x < -9.0f) ? spn : sp;
                sp = (x > 15.0f) ? x : sp;
                if (DIAG || POS) {
                    const int lr = warp_m * 32 + mt * 16 + (lane >> 2) + (i >> 1) * 8;
                    const int lc = warp_n * 64 + nl * 8 + (lane & 3) * 2 + (i & 1);
                    if (DIAG) { if (lr == lc) sp = 0.0f; }
                    if (POS)  { if (lr == lc) {            // global col == row ^ 8192 here
                        g_sppos[bi * 128 + lr] = sp;
                        g_sppos[bj * 128 + lc] = sp;
                    } }
                }
                rsum[mt][i >> 1] += sp;
                if (!DIAG) csum[nl * 2 + (i & 1)] += sp;
            }

    // ---- reductions (A/B smem dead now) ----
    __syncthreads();
    float* srow = (float*)(smem);          // [2(warp_n)][128]
    float* scol = (float*)(smem + 1024);   // [4(warp_m)][128]
    #pragma unroll
    for (int mt = 0; mt < 2; mt++)
        #pragma unroll
        for (int h = 0; h < 2; h++) {
            float v = rsum[mt][h];
            v += __shfl_xor_sync(0xffffffffu, v, 1);
            v += __shfl_xor_sync(0xffffffffu, v, 2);
            if ((lane & 3) == 0)
                srow[warp_n * 128 + warp_m * 32 + mt * 16 + (lane >> 2) + h * 8] = v;
        }
    if (!DIAG) {
        #pragma unroll
        for (int c = 0; c < 16; c++) {
            float v = csum[c];
            v += __shfl_xor_sync(0xffffffffu, v, 4);
            v += __shfl_xor_sync(0xffffffffu, v, 8);
            v += __shfl_xor_sync(0xffffffffu, v, 16);
            if (lane < 4)
                scol[warp_m * 128 + warp_n * 64 + (c >> 1) * 8 + lane * 2 + (c & 1)] = v;
        }
    }
    __syncthreads();
    if (tid < 128) {
        float rt = srow[tid] + srow[128 + tid];
        atomicAdd(&g_denom[bi * 128 + tid], rt);
        if (!DIAG) {
            float ct = scol[tid] + scol[128 + tid] + scol[256 + tid] + scol[384 + tid];
            atomicAdd(&g_denom[bj * 128 + tid], ct);
        }
    }
}

__global__ __launch_bounds__(THREADS, 2)
void fused_tri_kernel() {
    // exact rectangle -> upper-triangle map: 129 x 64 = 8256 CTAs, zero waste
    const int p = blockIdx.y;              // 0..63
    const int q = blockIdx.x;              // 0..128
    int bi = p, bj = p + q;
    if (bj >= 128) { bi = 127 - p; bj = q - 1; }
    extern __shared__ char smem[];
    const uint32_t sbase = smem_u32(smem);
    if (bi == bj)            tile_work<true,  false>(bi, bj, smem, sbase, threadIdx.x);
    else if (bj == (bi ^ 64))tile_work<false, true >(bi, bj, smem, sbase, threadIdx.x);
    else                     tile_work<false, false>(bi, bj, smem, sbase, threadIdx.x);
}

// ---------------- parallel finalize ----------------
__global__ void finalize_part() {
    __shared__ double red[256];
    const int i = blockIdx.x * 256 + threadIdx.x;     // 64*256 == NROWS exactly
    float spp = fmaxf(g_sppos[i], 1e-8f);
    float den = fmaxf(g_denom[i], 1e-8f);
    red[threadIdx.x] = (double)(logf(spp) - logf(den));
    __syncthreads();
    for (int o = 128; o > 0; o >>= 1) {
        if (threadIdx.x < o) red[threadIdx.x] += red[threadIdx.x + o];
        __syncthreads();
    }
    if (threadIdx.x == 0) atomicAdd(&g_total, red[0]);
}

__global__ void finalize_write(float* __restrict__ out) {
    out[0] = (float)(-g_total / (double)NROWS);
}

extern "C" void kernel_launch(void* const* d_in, const int* in_sizes, int n_in,
                              void* d_out, int out_size) {
    const float* za = (const float*)d_in[0];
    const float* zb = (const float*)d_in[1];
    float* out = (float*)d_out;

    cudaFuncSetAttribute(fused_tri_kernel, cudaFuncAttributeMaxDynamicSharedMemorySize, SM_TOTAL);

    convert_kernel<<<(NROWS * DDIM / 4 + 255) / 256, 256>>>(za, zb);
    dim3 grid(129, 64);                   // exact triangular cover
    fused_tri_kernel<<<grid, THREADS, SM_TOTAL>>>();
    finalize_part<<<64, 256>>>();
    finalize_write<<<1, 1>>>(out);
}